// round 5
// baseline (speedup 1.0000x reference)
#include <cuda_runtime.h>
#include <cstdint>
#include <cstddef>

#define NROWS 8192
#define NCLS  128
#define ROW_F4 2048              // NROWS/4
#define NN_F4 (NROWS * (size_t)NROWS / 4)

__device__ unsigned char g_cls[NROWS];

// ---- class extraction with in-bounds dtype probe ----
// View targets as int32 words. Probe ONLY the first NROWS words (in-bounds
// for both dtypes): int64 values in [0,128) => odd words all zero; int32
// targets => odd words are random classes, P(128 consecutive zeros)=128^-128.
__global__ __launch_bounds__(256) void k_cls(const int* __restrict__ w) {
    __shared__ int sh32;
    int t    = threadIdx.x;
    int base = blockIdx.x * 256;
    if (t == 0) sh32 = 0;
    __syncthreads();
    if (t < 128 && w[2 * t + 1] != 0) sh32 = 1;   // probe words 3..255 (<8192)
    __syncthreads();
    int i = base + t;
    int c = sh32 ? w[i] : w[2 * i];
    g_cls[i] = (unsigned char)c;
}

// ---- per-element math ----
__device__ __forceinline__ void elem(float simv, bool same,
                                     float pg, float ng, float rv,
                                     float& L, float& G) {
    float s = simv - 0.5f;
    float z = same ? (-2.0f * s) : (40.0f * s);
    bool active = (!same) || (simv < 1.0f);
    float t   = __expf(-fabsf(z));
    float op  = 1.0f + t;
    float inv = __fdividef(1.0f, op);
    float sp  = fmaxf(z, 0.0f) + __logf(op);          // stable softplus(z)
    float sg  = ((z >= 0.0f) ? 1.0f : t) * inv;       // stable sigmoid(z)
    float cf  = same ? pg : ng;
    L = active ? sp * rv : 0.0f;
    G = active ? cf * sg : 0.0f;
}

// ---- one block per row: load row, block-reduce counts, compute, store ----
__global__ __launch_bounds__(256) void k_main(const float* __restrict__ sim,
                                              float* __restrict__ out) {
    __shared__ int sh_red[8];
    int row = blockIdx.x;
    int t   = threadIdx.x;

    const float4* rp = reinterpret_cast<const float4*>(sim) + (size_t)row * ROW_F4;
    const uchar4* cp = reinterpret_cast<const uchar4*>(g_cls);
    int ci = g_cls[row];

    float4 sv[8];
    uchar4 cj[8];
#pragma unroll
    for (int k = 0; k < 8; ++k) {
        int c4 = t + k * 256;
        sv[k] = __ldcs(rp + c4);
        cj[k] = cp[c4];
    }

    // count same-class (all) and same-class&&sim<1 (pos), packed 16+16
    int acc = 0;
#pragma unroll
    for (int k = 0; k < 8; ++k) {
        int sx = (cj[k].x == ci), sy = (cj[k].y == ci),
            sz = (cj[k].z == ci), sw = (cj[k].w == ci);
        acc += (sx << 16) + (sx & (sv[k].x < 1.0f));
        acc += (sy << 16) + (sy & (sv[k].y < 1.0f));
        acc += (sz << 16) + (sz & (sv[k].z < 1.0f));
        acc += (sw << 16) + (sw & (sv[k].w < 1.0f));
    }
    acc = __reduce_add_sync(0xffffffffu, acc);
    if ((t & 31) == 0) sh_red[t >> 5] = acc;
    __syncthreads();
    int tot = 0;
#pragma unroll
    for (int i = 0; i < 8; ++i) tot += sh_red[i];

    int pos_cnt  = tot & 0xffff;
    int same_cnt = tot >> 16;
    int negraw   = NROWS - same_cnt;
    float rv = (negraw > 0) ? 1.0f : 0.0f;
    float pg = -2.0f * rv / (float)((pos_cnt > 1) ? pos_cnt : 1);
    float ng = 40.0f * rv / (float)((negraw  > 1) ? negraw  : 1);

    float4* lossb = reinterpret_cast<float4*>(out) + (size_t)row * ROW_F4;
    float4* gradb = reinterpret_cast<float4*>(out) + NN_F4 + (size_t)row * ROW_F4;
#pragma unroll
    for (int k = 0; k < 8; ++k) {
        int c4 = t + k * 256;
        float4 Lo, Gr;
        elem(sv[k].x, cj[k].x == ci, pg, ng, rv, Lo.x, Gr.x);
        elem(sv[k].y, cj[k].y == ci, pg, ng, rv, Lo.y, Gr.y);
        elem(sv[k].z, cj[k].z == ci, pg, ng, rv, Lo.z, Gr.z);
        elem(sv[k].w, cj[k].w == ci, pg, ng, rv, Lo.w, Gr.w);
        __stcs(lossb + c4, Lo);
        __stcs(gradb + c4, Gr);
    }
}

extern "C" void kernel_launch(void* const* d_in, const int* in_sizes, int n_in,
                              void* d_out, int out_size) {
    const float* sim = (const float*)d_in[0];
    const int*   tgw = (const int*)d_in[1];     // int32 view of targets
    float*       out = (float*)d_out;

    k_cls<<<NROWS / 256, 256>>>(tgw);
    k_main<<<NROWS, 256>>>(sim, out);
}

// round 6
// speedup vs baseline: 1.0737x; 1.0737x over previous
#include <cuda_runtime.h>
#include <cstdint>
#include <cstddef>

#define NROWS 8192
#define ROW_F4 2048              // NROWS/4
#define NN_F4 (NROWS * (size_t)NROWS / 4)

__device__ unsigned char g_cls[NROWS];

// ---- class extraction with in-bounds dtype probe ----
// View targets as int32 words. Probe ONLY the first NROWS words (in-bounds
// for both dtypes): int64 values in [0,128) => odd words all zero; int32
// targets => odd words are random classes, P(128 consecutive zeros)=128^-128.
__global__ __launch_bounds__(256) void k_cls(const int* __restrict__ w) {
    __shared__ int sh32;
    int t    = threadIdx.x;
    int base = blockIdx.x * 256;
    if (t == 0) sh32 = 0;
    __syncthreads();
    if (t < 128 && w[2 * t + 1] != 0) sh32 = 1;
    __syncthreads();
    int i = base + t;
    int c = sh32 ? w[i] : w[2 * i];
    g_cls[i] = (unsigned char)c;
}

// ---- per-element math ----
__device__ __forceinline__ void elem(float simv, bool same,
                                     float pg, float ng, float rv,
                                     float& L, float& G) {
    float s = simv - 0.5f;
    float z = same ? (-2.0f * s) : (40.0f * s);
    bool active = (!same) || (simv < 1.0f);
    float t   = __expf(-fabsf(z));
    float op  = 1.0f + t;
    float inv = __fdividef(1.0f, op);
    float sp  = fmaxf(z, 0.0f) + __logf(op);          // stable softplus(z)
    float sg  = ((z >= 0.0f) ? 1.0f : t) * inv;       // stable sigmoid(z)
    float cf  = same ? pg : ng;
    L = active ? sp * rv : 0.0f;
    G = active ? cf * sg : 0.0f;
}

// ---- one block per row ----
// Phase A: scan class words; load sim float4 ONLY where a byte matches the
//          row class (~3% of words) to count pos pairs. Nothing held across
//          the barrier -> low regs, high occupancy.
// Phase B: stream the full row: load, compute, store.
__global__ __launch_bounds__(256, 5) void k_main(const float* __restrict__ sim,
                                                 float* __restrict__ out) {
    __shared__ int sh_red[8];
    int row = blockIdx.x;
    int t   = threadIdx.x;

    const float4*       rp = reinterpret_cast<const float4*>(sim) + (size_t)row * ROW_F4;
    const unsigned int* cw = reinterpret_cast<const unsigned int*>(g_cls);
    int ci = g_cls[row];
    unsigned int ci4 = (unsigned int)ci * 0x01010101u;

    // Phase A: counts
    int acc = 0;
#pragma unroll
    for (int k = 0; k < 8; ++k) {
        int c4 = t + k * 256;
        unsigned int m = __vcmpeq4(cw[c4], ci4);
        if (m) {
            float4 sv = rp[c4];                 // cached load, rare
            int sc = 0, pc = 0;
            if (m & 0x000000ffu) { sc++; pc += (sv.x < 1.0f); }
            if (m & 0x0000ff00u) { sc++; pc += (sv.y < 1.0f); }
            if (m & 0x00ff0000u) { sc++; pc += (sv.z < 1.0f); }
            if (m & 0xff000000u) { sc++; pc += (sv.w < 1.0f); }
            acc += (sc << 16) + pc;
        }
    }
    acc = __reduce_add_sync(0xffffffffu, acc);
    if ((t & 31) == 0) sh_red[t >> 5] = acc;
    __syncthreads();
    int tot = 0;
#pragma unroll
    for (int i = 0; i < 8; ++i) tot += sh_red[i];

    int pos_cnt  = tot & 0xffff;
    int same_cnt = tot >> 16;
    int negraw   = NROWS - same_cnt;
    float rv = (negraw > 0) ? 1.0f : 0.0f;
    float pg = -2.0f * rv / (float)((pos_cnt > 1) ? pos_cnt : 1);
    float ng = 40.0f * rv / (float)((negraw  > 1) ? negraw  : 1);

    // Phase B: streaming pass
    float4* lossb = reinterpret_cast<float4*>(out) + (size_t)row * ROW_F4;
    float4* gradb = reinterpret_cast<float4*>(out) + NN_F4 + (size_t)row * ROW_F4;
#pragma unroll 4
    for (int k = 0; k < 8; ++k) {
        int c4 = t + k * 256;
        float4 sv = __ldcs(rp + c4);
        unsigned int m = __vcmpeq4(cw[c4], ci4);
        float4 Lo, Gr;
        elem(sv.x, (m & 0x000000ffu) != 0u, pg, ng, rv, Lo.x, Gr.x);
        elem(sv.y, (m & 0x0000ff00u) != 0u, pg, ng, rv, Lo.y, Gr.y);
        elem(sv.z, (m & 0x00ff0000u) != 0u, pg, ng, rv, Lo.z, Gr.z);
        elem(sv.w, (m & 0xff000000u) != 0u, pg, ng, rv, Lo.w, Gr.w);
        __stcs(lossb + c4, Lo);
        __stcs(gradb + c4, Gr);
    }
}

extern "C" void kernel_launch(void* const* d_in, const int* in_sizes, int n_in,
                              void* d_out, int out_size) {
    const float* sim = (const float*)d_in[0];
    const int*   tgw = (const int*)d_in[1];     // int32 view of targets
    float*       out = (float*)d_out;

    k_cls<<<NROWS / 256, 256>>>(tgw);
    k_main<<<NROWS, 256>>>(sim, out);
}

// round 7
// speedup vs baseline: 1.0878x; 1.0132x over previous
#include <cuda_runtime.h>
#include <cstdint>
#include <cstddef>

#define NROWS 8192
#define ROW_F4 2048              // NROWS/4
#define NN_F4 (NROWS * (size_t)NROWS / 4)

__device__ unsigned char g_cls[NROWS];
__device__ float4        g_params[NROWS];  // {pg, ng, rv, pad}

// ---- class extraction with in-bounds dtype probe ----
// View targets as int32 words. Probe ONLY words < NROWS (in-bounds for both
// dtypes): int64 values in [0,128) => odd words all zero; int32 targets =>
// P(128 consecutive odd words zero) = 128^-128 ~ 0.
__global__ __launch_bounds__(256) void k_cls(const int* __restrict__ w) {
    __shared__ int sh32;
    int t    = threadIdx.x;
    int base = blockIdx.x * 256;
    if (t == 0) sh32 = 0;
    __syncthreads();
    if (t < 128 && w[2 * t + 1] != 0) sh32 = 1;   // indices <= 255 < NROWS
    __syncthreads();
    int i = base + t;
    int c = sh32 ? w[i] : w[2 * i];
    g_cls[i] = (unsigned char)c;
}

// ---- per-row params: warp per row, class-word scan + rare sim gathers ----
__global__ __launch_bounds__(256) void k_rowparams(const float* __restrict__ sim) {
    int row  = blockIdx.x * 8 + (threadIdx.x >> 5);
    int lane = threadIdx.x & 31;
    const unsigned int* cw = reinterpret_cast<const unsigned int*>(g_cls);
    const float4* rp = reinterpret_cast<const float4*>(sim) + (size_t)row * ROW_F4;
    unsigned int ci4 = (unsigned int)g_cls[row] * 0x01010101u;

    int acc = 0;                       // same<<16 | pos
    for (int j = lane; j < ROW_F4; j += 32) {
        unsigned int m = __vcmpeq4(cw[j], ci4);
        if (m) {
            float4 sv = rp[j];
            int sc = __popc(m) >> 3;
            int pc = 0;
            if (m & 0x000000ffu) pc += (sv.x < 1.0f);
            if (m & 0x0000ff00u) pc += (sv.y < 1.0f);
            if (m & 0x00ff0000u) pc += (sv.z < 1.0f);
            if (m & 0xff000000u) pc += (sv.w < 1.0f);
            acc += (sc << 16) + pc;
        }
    }
    acc = __reduce_add_sync(0xffffffffu, acc);
    if (lane == 0) {
        int pos_cnt  = acc & 0xffff;
        int same_cnt = acc >> 16;
        int negraw   = NROWS - same_cnt;
        float rv = (negraw > 0) ? 1.0f : 0.0f;
        float pg = -2.0f * rv / (float)((pos_cnt > 1) ? pos_cnt : 1);
        float ng = 40.0f * rv / (float)((negraw  > 1) ? negraw  : 1);
        g_params[row] = make_float4(pg, ng, rv, 0.0f);
    }
}

// ---- per-element math ----
__device__ __forceinline__ void elem(float simv, bool same,
                                     float pg, float ng, float rv,
                                     float& L, float& G) {
    float s = simv - 0.5f;
    float z = same ? (-2.0f * s) : (40.0f * s);
    bool active = (!same) || (simv < 1.0f);
    float t   = __expf(-fabsf(z));
    float op  = 1.0f + t;
    float inv = __fdividef(1.0f, op);
    float sp  = fmaxf(z, 0.0f) + __logf(op);          // stable softplus(z)
    float sg  = ((z >= 0.0f) ? 1.0f : t) * inv;       // stable sigmoid(z)
    float cf  = same ? pg : ng;
    L = active ? sp * rv : 0.0f;
    G = active ? cf * sg : 0.0f;
}

// ---- pure streaming main: each block = quarter row (row uniform per block)
__global__ __launch_bounds__(256) void k_main(const float* __restrict__ sim,
                                              float* __restrict__ out) {
    int row  = blockIdx.x >> 2;                       // block-uniform
    int base = ((blockIdx.x & 3) << 9) + threadIdx.x; // f4 index within row

    const float4*       rp = reinterpret_cast<const float4*>(sim) + (size_t)row * ROW_F4;
    const unsigned int* cw = reinterpret_cast<const unsigned int*>(g_cls);
    float4 p = g_params[row];
    unsigned int ci4 = (unsigned int)g_cls[row] * 0x01010101u;

    int c40 = base, c41 = base + 256;
    float4 sv0 = __ldcs(rp + c40);
    float4 sv1 = __ldcs(rp + c41);
    unsigned int m0 = __vcmpeq4(cw[c40], ci4);
    unsigned int m1 = __vcmpeq4(cw[c41], ci4);

    float4* lossb = reinterpret_cast<float4*>(out) + (size_t)row * ROW_F4;
    float4* gradb = reinterpret_cast<float4*>(out) + NN_F4 + (size_t)row * ROW_F4;

    float4 Lo, Gr;
    elem(sv0.x, (m0 & 0x000000ffu) != 0u, p.x, p.y, p.z, Lo.x, Gr.x);
    elem(sv0.y, (m0 & 0x0000ff00u) != 0u, p.x, p.y, p.z, Lo.y, Gr.y);
    elem(sv0.z, (m0 & 0x00ff0000u) != 0u, p.x, p.y, p.z, Lo.z, Gr.z);
    elem(sv0.w, (m0 & 0xff000000u) != 0u, p.x, p.y, p.z, Lo.w, Gr.w);
    __stcs(lossb + c40, Lo);
    __stcs(gradb + c40, Gr);

    elem(sv1.x, (m1 & 0x000000ffu) != 0u, p.x, p.y, p.z, Lo.x, Gr.x);
    elem(sv1.y, (m1 & 0x0000ff00u) != 0u, p.x, p.y, p.z, Lo.y, Gr.y);
    elem(sv1.z, (m1 & 0x00ff0000u) != 0u, p.x, p.y, p.z, Lo.z, Gr.z);
    elem(sv1.w, (m1 & 0xff000000u) != 0u, p.x, p.y, p.z, Lo.w, Gr.w);
    __stcs(lossb + c41, Lo);
    __stcs(gradb + c41, Gr);
}

extern "C" void kernel_launch(void* const* d_in, const int* in_sizes, int n_in,
                              void* d_out, int out_size) {
    const float* sim = (const float*)d_in[0];
    const int*   tgw = (const int*)d_in[1];     // int32 view of targets
    float*       out = (float*)d_out;

    k_cls<<<NROWS / 256, 256>>>(tgw);
    k_rowparams<<<NROWS / 8, 256>>>(sim);
    k_main<<<NROWS * 4, 256>>>(sim, out);
}

// round 8
// speedup vs baseline: 1.1163x; 1.0262x over previous
#include <cuda_runtime.h>
#include <cstdint>
#include <cstddef>

#define NROWS 8192
#define ROW_F4 2048              // NROWS/4
#define ROW_SHIFT 11
#define NN_F4 (NROWS * (size_t)NROWS / 4)

__device__ unsigned char g_cls[NROWS];
__device__ float4        g_params[NROWS];  // {pg, ng, rv, pad}

// ---- fused prep: dtype probe + class pack (smem) + per-row counts ----
// Each block rebuilds the full class array in shared memory (targets reads
// are L2-hot; redundancy across blocks is free), then its 8 warps each
// compute one row's params and write that row's class byte.
__global__ __launch_bounds__(256) void k_prep(const int* __restrict__ w,
                                              const float* __restrict__ sim) {
    __shared__ unsigned int sh_cls[ROW_F4];   // 8 KB: class byte per column
    __shared__ int sh32;
    int t = threadIdx.x;

    // dtype probe, in-bounds for both dtypes (words < NROWS):
    // int64 values in [0,128) => odd words zero; int32 => nonzero w.h.p.
    if (t == 0) sh32 = 0;
    __syncthreads();
    if (t < 128 && w[2 * t + 1] != 0) sh32 = 1;
    __syncthreads();
    int is32 = sh32;

    // pack class bytes into smem words: word j = classes[4j..4j+3]
#pragma unroll
    for (int j = t; j < ROW_F4; j += 256) {
        int b0, b1, b2, b3;
        if (is32) {
            int4 v = reinterpret_cast<const int4*>(w)[j];
            b0 = v.x; b1 = v.y; b2 = v.z; b3 = v.w;
        } else {
            b0 = w[8 * j]; b1 = w[8 * j + 2]; b2 = w[8 * j + 4]; b3 = w[8 * j + 6];
        }
        sh_cls[j] = (unsigned int)(b0 & 255) | ((unsigned int)(b1 & 255) << 8) |
                    ((unsigned int)(b2 & 255) << 16) | ((unsigned int)(b3 & 255) << 24);
    }
    __syncthreads();

    int wid  = t >> 5, lane = t & 31;
    int row  = blockIdx.x * 8 + wid;
    unsigned int ci  = (sh_cls[row >> 2] >> ((row & 3) * 8)) & 255u;
    unsigned int ci4 = ci * 0x01010101u;
    const float4* rp = reinterpret_cast<const float4*>(sim) + (size_t)row * ROW_F4;

    int acc = 0;                               // same<<16 | pos
    for (int j = lane; j < ROW_F4; j += 32) {
        unsigned int m = __vcmpeq4(sh_cls[j], ci4);
        if (m) {
            float4 sv = rp[j];                 // rare (~3% of words)
            int sc = __popc(m) >> 3;
            int pc = 0;
            if (m & 0x000000ffu) pc += (sv.x < 1.0f);
            if (m & 0x0000ff00u) pc += (sv.y < 1.0f);
            if (m & 0x00ff0000u) pc += (sv.z < 1.0f);
            if (m & 0xff000000u) pc += (sv.w < 1.0f);
            acc += (sc << 16) + pc;
        }
    }
    acc = __reduce_add_sync(0xffffffffu, acc);
    if (lane == 0) {
        int pos_cnt  = acc & 0xffff;
        int same_cnt = acc >> 16;
        int negraw   = NROWS - same_cnt;
        float rv = (negraw > 0) ? 1.0f : 0.0f;
        float pg = -2.0f * rv / (float)((pos_cnt > 1) ? pos_cnt : 1);
        float ng = 40.0f * rv / (float)((negraw  > 1) ? negraw  : 1);
        g_params[row] = make_float4(pg, ng, rv, 0.0f);
        g_cls[row] = (unsigned char)ci;        // blocks jointly cover all rows
    }
}

// ---- per-element math ----
__device__ __forceinline__ void elem(float simv, bool same,
                                     float pg, float ng, float rv,
                                     float& L, float& G) {
    float s = simv - 0.5f;
    float z = same ? (-2.0f * s) : (40.0f * s);
    bool active = (!same) || (simv < 1.0f);
    float t   = __expf(-fabsf(z));
    float op  = 1.0f + t;
    float inv = __fdividef(1.0f, op);
    float sp  = fmaxf(z, 0.0f) + __logf(op);          // stable softplus(z)
    float sg  = ((z >= 0.0f) ? 1.0f : t) * inv;       // stable sigmoid(z)
    float cf  = same ? pg : ng;
    L = active ? sp * rv : 0.0f;
    G = active ? cf * sg : 0.0f;
}

// ---- main streaming kernel: EXACT R3 structure (measured ~118us) ----
__global__ __launch_bounds__(256) void k_main(const float* __restrict__ sim,
                                              float* __restrict__ out) {
    int idx  = blockIdx.x * blockDim.x + threadIdx.x;   // float4 index
    int row  = idx >> ROW_SHIFT;
    int col4 = idx & (ROW_F4 - 1);

    float4 sv = __ldcs(reinterpret_cast<const float4*>(sim) + idx);
    uchar4 cj = reinterpret_cast<const uchar4*>(g_cls)[col4];
    int    ci = g_cls[row];
    float4 p  = g_params[row];

    float4 Lo, Gr;
    elem(sv.x, cj.x == ci, p.x, p.y, p.z, Lo.x, Gr.x);
    elem(sv.y, cj.y == ci, p.x, p.y, p.z, Lo.y, Gr.y);
    elem(sv.z, cj.z == ci, p.x, p.y, p.z, Lo.z, Gr.z);
    elem(sv.w, cj.w == ci, p.x, p.y, p.z, Lo.w, Gr.w);

    float4* lossb = reinterpret_cast<float4*>(out);
    float4* gradb = lossb + NN_F4;
    __stcs(lossb + idx, Lo);
    __stcs(gradb + idx, Gr);
}

extern "C" void kernel_launch(void* const* d_in, const int* in_sizes, int n_in,
                              void* d_out, int out_size) {
    const float* sim = (const float*)d_in[0];
    const int*   tgw = (const int*)d_in[1];     // int32 view of targets
    float*       out = (float*)d_out;

    k_prep<<<NROWS / 8, 256>>>(tgw, sim);
    k_main<<<(int)(NN_F4 / 256), 256>>>(sim, out);
}